// round 2
// baseline (speedup 1.0000x reference)
#include <cuda_runtime.h>
#include <math.h>

#define N_NODES   100000
#define N_EDGES   1600000
#define NUM_GRAPHS 512
#define HID       128

// ---------------- static device scratch (no allocations allowed) -------------
__device__ __align__(16) float g_buf0[(size_t)N_NODES * HID];
__device__ __align__(16) float g_buf1[(size_t)N_NODES * HID];
__device__ __align__(16) float g_buf2[(size_t)N_NODES * HID];
__device__ float g_dinv[N_NODES];
__device__ int   g_cnt[N_NODES];      // in-degree (targets), excl self-loop
__device__ int   g_fill[N_NODES];     // CSR fill cursors
__device__ int   g_rowptr[N_NODES + 1];
__device__ int   g_srcs[N_EDGES];     // CSR adjacency: sources per target
__device__ float g_pool[NUM_GRAPHS * HID];
__device__ float g_poolcnt[NUM_GRAPHS];

// ---------------- init -------------------------------------------------------
__global__ void k_init() {
    int i = blockIdx.x * blockDim.x + threadIdx.x;
    if (i < N_NODES) { g_cnt[i] = 0; g_fill[i] = 0; }
    if (i < NUM_GRAPHS * HID) g_pool[i] = 0.f;
    if (i < NUM_GRAPHS) g_poolcnt[i] = 0.f;
}

// ---------------- degree histogram over edge targets (edge_index is int32) ---
__global__ void k_hist(const int* __restrict__ ei) {
    int e = blockIdx.x * blockDim.x + threadIdx.x;
    if (e < N_EDGES) atomicAdd(&g_cnt[ei[N_EDGES + e]], 1);
}

// ---------------- single-block exclusive scan + dinv -------------------------
__global__ void k_scan() {
    const int T = 1024;
    const int CH = (N_NODES + T - 1) / T;   // 98
    int t = threadIdx.x;
    int s = t * CH;
    int e = s + CH; if (e > N_NODES) e = N_NODES;

    int sum = 0;
    for (int i = s; i < e; i++) sum += g_cnt[i];

    __shared__ int ss[T];
    ss[t] = sum;
    __syncthreads();
    for (int off = 1; off < T; off <<= 1) {
        int v = (t >= off) ? ss[t - off] : 0;
        __syncthreads();
        ss[t] += v;
        __syncthreads();
    }
    int run = (t > 0) ? ss[t - 1] : 0;
    for (int i = s; i < e; i++) {
        int c = g_cnt[i];
        g_rowptr[i] = run;
        run += c;
        g_dinv[i] = rsqrtf((float)(c + 1));   // +1 self-loop, always > 0
    }
    if (t == T - 1) g_rowptr[N_NODES] = ss[T - 1];
}

// ---------------- CSR fill ---------------------------------------------------
__global__ void k_fill(const int* __restrict__ ei) {
    int e = blockIdx.x * blockDim.x + threadIdx.x;
    if (e < N_EDGES) {
        int row = ei[e];
        int col = ei[N_EDGES + e];
        int pos = g_rowptr[col] + atomicAdd(&g_fill[col], 1);
        g_srcs[pos] = row;
    }
}

// ---------------- GEMM: out = (A @ W) * dinv[row]  ---------------------------
// A: [N,128] row-major, W: [128,128] row-major. Block: 64 rows x 128 cols, 256 thr.
__global__ void __launch_bounds__(256) k_gemm_scale(
        const float* __restrict__ A, const float* __restrict__ W,
        float* __restrict__ out) {
    __shared__ float As[64][32];
    __shared__ float Bs[32][128];
    int tid  = threadIdx.x;
    int row0 = blockIdx.x * 64;
    int tr = tid >> 5;        // 0..7  -> 8 rows each
    int tc = tid & 31;        // 0..31 -> 4 cols each

    float4 acc[8];
#pragma unroll
    for (int i = 0; i < 8; i++) acc[i] = make_float4(0.f, 0.f, 0.f, 0.f);

    for (int kt = 0; kt < 128; kt += 32) {
#pragma unroll
        for (int i = 0; i < 2; i++) {                 // A tile: 64x32
            int idx = tid + i * 256;
            int r = idx >> 3, q = idx & 7;
            int gr = row0 + r;
            float4 v = make_float4(0.f, 0.f, 0.f, 0.f);
            if (gr < N_NODES)
                v = *(const float4*)(A + (size_t)gr * 128 + kt + q * 4);
            *(float4*)&As[r][q * 4] = v;
        }
#pragma unroll
        for (int i = 0; i < 4; i++) {                 // W tile: 32x128
            int idx = tid + i * 256;
            int kr = idx >> 5, q = idx & 31;
            *(float4*)&Bs[kr][q * 4] =
                *(const float4*)(W + (size_t)(kt + kr) * 128 + q * 4);
        }
        __syncthreads();
#pragma unroll
        for (int k = 0; k < 32; k++) {
            float4 bv = *(float4*)&Bs[k][tc * 4];
#pragma unroll
            for (int i = 0; i < 8; i++) {
                float a = As[tr * 8 + i][k];          // warp-uniform -> broadcast
                acc[i].x += a * bv.x;
                acc[i].y += a * bv.y;
                acc[i].z += a * bv.z;
                acc[i].w += a * bv.w;
            }
        }
        __syncthreads();
    }
#pragma unroll
    for (int i = 0; i < 8; i++) {
        int gr = row0 + tr * 8 + i;
        if (gr < N_NODES) {
            float d = g_dinv[gr];
            float4 v = acc[i];
            v.x *= d; v.y *= d; v.z *= d; v.w *= d;
            *(float4*)(out + (size_t)gr * 128 + tc * 4) = v;
        }
    }
}

// ---------------- gather (pull): out[i] = relu(dinv[i]*(t[i]+sum t[j]) + b) --
// one warp per node, lane handles 4 contiguous cols (float4)
__global__ void __launch_bounds__(256) k_gather(
        const float* __restrict__ ts, const float* __restrict__ bias,
        float* __restrict__ out) {
    int w    = (blockIdx.x * blockDim.x + threadIdx.x) >> 5;
    int lane = threadIdx.x & 31;
    if (w >= N_NODES) return;

    const float* tsl = ts + 4 * lane;
    float4 acc = *(const float4*)(tsl + (size_t)w * 128);   // self-loop term

    int e0 = g_rowptr[w];
    int e1 = g_rowptr[w + 1];
    for (int eb = e0; eb < e1; eb += 32) {
        int cnt = e1 - eb; if (cnt > 32) cnt = 32;
        int s = (lane < cnt) ? g_srcs[eb + lane] : 0;
        for (int j = 0; j < cnt; j++) {
            int sj = __shfl_sync(0xffffffffu, s, j);
            float4 v = *(const float4*)(tsl + (size_t)sj * 128);
            acc.x += v.x; acc.y += v.y; acc.z += v.z; acc.w += v.w;
        }
    }
    float  d  = g_dinv[w];
    float4 bb = *(const float4*)(bias + 4 * lane);
    float4 o;
    o.x = fmaxf(acc.x * d + bb.x, 0.f);
    o.y = fmaxf(acc.y * d + bb.y, 0.f);
    o.z = fmaxf(acc.z * d + bb.z, 0.f);
    o.w = fmaxf(acc.w * d + bb.w, 0.f);
    *(float4*)(out + (size_t)w * 128 + 4 * lane) = o;
}

// ---------------- pooling: batch is sorted -> smem window accumulation -------
#define POOL_NODES 256
#define WIN 16
__global__ void __launch_bounds__(128) k_pool(
        const float* __restrict__ h, const int* __restrict__ batch) {
    int n0 = blockIdx.x * POOL_NODES;
    int n1 = n0 + POOL_NODES; if (n1 > N_NODES) n1 = N_NODES;
    if (n0 >= N_NODES) return;
    int c = threadIdx.x;                       // 128 threads, one col each

    __shared__ float sacc[WIN][128];
    __shared__ int   scnt[WIN];

    int b0 = batch[n0];
    int b1 = batch[n1 - 1];

    for (int wb = b0; wb <= b1; wb += WIN) {
        int we = wb + WIN - 1; if (we > b1) we = b1;
#pragma unroll
        for (int wi = 0; wi < WIN; wi++) sacc[wi][c] = 0.f;
        if (c < WIN) scnt[c] = 0;
        __syncthreads();
        for (int n = n0; n < n1; n++) {
            int g = batch[n];
            if (g >= wb && g <= we) {
                sacc[g - wb][c] += h[(size_t)n * 128 + c];
                if (c == 0) scnt[g - wb]++;
            }
        }
        __syncthreads();
        for (int wi = 0; wi <= we - wb; wi++)
            atomicAdd(&g_pool[(wb + wi) * 128 + c], sacc[wi][c]);
        if (c == 0)
            for (int wi = 0; wi <= we - wb; wi++)
                atomicAdd(&g_poolcnt[wb + wi], (float)scnt[wi]);
        __syncthreads();
    }
}

// ---------------- MLP head: out = relu(p@Wm1+bm1) @ Wm2 + bm2 ----------------
__global__ void __launch_bounds__(128) k_mlp(
        const float* __restrict__ Wm1, const float* __restrict__ bm1,
        const float* __restrict__ Wm2, const float* __restrict__ bm2,
        float* __restrict__ out) {
    int g = blockIdx.x;
    int t = threadIdx.x;
    __shared__ float p[128];
    __shared__ float z[64];
    float cnt = fmaxf(g_poolcnt[g], 1.f);
    p[t] = g_pool[g * 128 + t] / cnt;
    __syncthreads();
    if (t < 64) {
        float a = bm1[t];
#pragma unroll 8
        for (int c = 0; c < 128; c++) a += p[c] * Wm1[c * 64 + t];
        z[t] = fmaxf(a, 0.f);
    }
    __syncthreads();
    if (t < 32) {
        float a = bm2[t];
#pragma unroll 8
        for (int j = 0; j < 64; j++) a += z[j] * Wm2[j * 32 + t];
        out[g * 32 + t] = a;
    }
}

// ---------------- launch -----------------------------------------------------
extern "C" void kernel_launch(void* const* d_in, const int* in_sizes, int n_in,
                              void* d_out, int out_size) {
    // Resolve inputs by element count (robust to serialization order).
    // Sizes: x=12.8M, edge_index=3.2M, batch=100k, W*=16384 (x3, in order),
    // b*=128 (x3, in order), Wm1=8192, bm1=64, Wm2=2048, bm2=32.
    const float *x = 0, *W[3] = {0,0,0}, *b[3] = {0,0,0};
    const float *Wm1 = 0, *bm1 = 0, *Wm2 = 0, *bm2 = 0;
    const int *ei = 0, *batch = 0;
    int wi = 0, bi = 0;
    for (int i = 0; i < n_in; i++) {
        long long s = in_sizes[i];
        if      (s == (long long)N_NODES * HID) x     = (const float*)d_in[i];
        else if (s == 2LL * N_EDGES)            ei    = (const int*)d_in[i];
        else if (s == N_NODES)                  batch = (const int*)d_in[i];
        else if (s == HID * HID) { if (wi < 3) W[wi++] = (const float*)d_in[i]; }
        else if (s == HID)       { if (bi < 3) b[bi++] = (const float*)d_in[i]; }
        else if (s == HID * (HID / 2))          Wm1   = (const float*)d_in[i];
        else if (s == HID / 2)                  bm1   = (const float*)d_in[i];
        else if (s == (HID / 2) * 32)           Wm2   = (const float*)d_in[i];
        else if (s == 32)                       bm2   = (const float*)d_in[i];
    }
    float* out = (float*)d_out;

    float *buf0, *buf1, *buf2;
    cudaGetSymbolAddress((void**)&buf0, g_buf0);
    cudaGetSymbolAddress((void**)&buf1, g_buf1);
    cudaGetSymbolAddress((void**)&buf2, g_buf2);

    const int EB = (N_EDGES + 255) / 256;
    const int NB = (N_NODES + 255) / 256;
    const int GB = (N_NODES + 63) / 64;
    const int WB = (N_NODES * 32 + 255) / 256;
    const int PB = (N_NODES + POOL_NODES - 1) / POOL_NODES;

    k_init<<<NB, 256>>>();
    k_hist<<<EB, 256>>>(ei);
    k_scan<<<1, 1024>>>();
    k_fill<<<EB, 256>>>(ei);

    // layer 1: x -> buf1
    k_gemm_scale<<<GB, 256>>>(x, W[0], buf0);
    k_gather<<<WB, 256>>>(buf0, b[0], buf1);
    // layer 2: buf1 -> buf2
    k_gemm_scale<<<GB, 256>>>(buf1, W[1], buf0);
    k_gather<<<WB, 256>>>(buf0, b[1], buf2);
    // layer 3: buf2 -> buf1
    k_gemm_scale<<<GB, 256>>>(buf2, W[2], buf0);
    k_gather<<<WB, 256>>>(buf0, b[2], buf1);

    k_pool<<<PB, 128>>>(buf1, batch);
    k_mlp<<<NUM_GRAPHS, 128>>>(Wm1, bm1, Wm2, bm2, out);
}

// round 3
// speedup vs baseline: 1.0028x; 1.0028x over previous
#include <cuda_runtime.h>
#include <math.h>

#define N_NODES   100000
#define N_EDGES   1600000
#define NUM_GRAPHS 512
#define HID       128

// ---------------- static device scratch (no allocations allowed) -------------
__device__ __align__(16) float g_buf0[(size_t)N_NODES * HID];
__device__ __align__(16) float g_buf1[(size_t)N_NODES * HID];
__device__ __align__(16) float g_buf2[(size_t)N_NODES * HID];
__device__ float g_dinv[N_NODES];
__device__ int   g_cnt[N_NODES];      // in-degree (targets), excl self-loop
__device__ int   g_fill[N_NODES];     // CSR fill cursors
__device__ int   g_rowptr[N_NODES + 1];
__device__ int   g_srcs[N_EDGES];     // CSR adjacency: sources per target
__device__ float g_pool[NUM_GRAPHS * HID];
__device__ float g_poolcnt[NUM_GRAPHS];

// ---------------- init -------------------------------------------------------
__global__ void k_init() {
    int i = blockIdx.x * blockDim.x + threadIdx.x;
    if (i < N_NODES) { g_cnt[i] = 0; g_fill[i] = 0; }
    if (i < NUM_GRAPHS * HID) g_pool[i] = 0.f;
    if (i < NUM_GRAPHS) g_poolcnt[i] = 0.f;
}

// ---------------- degree histogram over edge targets (edge_index is int32) ---
__global__ void k_hist(const int* __restrict__ ei) {
    int e = blockIdx.x * blockDim.x + threadIdx.x;
    if (e < N_EDGES) atomicAdd(&g_cnt[ei[N_EDGES + e]], 1);
}

// ---------------- single-block exclusive scan + dinv -------------------------
__global__ void k_scan() {
    const int T = 1024;
    const int CH = (N_NODES + T - 1) / T;   // 98
    int t = threadIdx.x;
    int s = t * CH;
    int e = s + CH; if (e > N_NODES) e = N_NODES;

    int sum = 0;
    for (int i = s; i < e; i++) sum += g_cnt[i];

    __shared__ int ss[T];
    ss[t] = sum;
    __syncthreads();
    for (int off = 1; off < T; off <<= 1) {
        int v = (t >= off) ? ss[t - off] : 0;
        __syncthreads();
        ss[t] += v;
        __syncthreads();
    }
    int run = (t > 0) ? ss[t - 1] : 0;
    for (int i = s; i < e; i++) {
        int c = g_cnt[i];
        g_rowptr[i] = run;
        run += c;
        g_dinv[i] = rsqrtf((float)(c + 1));   // +1 self-loop, always > 0
    }
    if (t == T - 1) g_rowptr[N_NODES] = ss[T - 1];
}

// ---------------- CSR fill ---------------------------------------------------
__global__ void k_fill(const int* __restrict__ ei) {
    int e = blockIdx.x * blockDim.x + threadIdx.x;
    if (e < N_EDGES) {
        int row = ei[e];
        int col = ei[N_EDGES + e];
        int pos = g_rowptr[col] + atomicAdd(&g_fill[col], 1);
        g_srcs[pos] = row;
    }
}

// ---------------- GEMM: out = (A @ W) * dinv[row]  ---------------------------
// A: [N,128] row-major, W: [128,128] row-major. Block: 64 rows x 128 cols, 256 thr.
__global__ void __launch_bounds__(256) k_gemm_scale(
        const float* __restrict__ A, const float* __restrict__ W,
        float* __restrict__ out) {
    __shared__ float As[64][32];
    __shared__ float Bs[32][128];
    int tid  = threadIdx.x;
    int row0 = blockIdx.x * 64;
    int tr = tid >> 5;        // 0..7  -> 8 rows each
    int tc = tid & 31;        // 0..31 -> 4 cols each

    float4 acc[8];
#pragma unroll
    for (int i = 0; i < 8; i++) acc[i] = make_float4(0.f, 0.f, 0.f, 0.f);

    for (int kt = 0; kt < 128; kt += 32) {
#pragma unroll
        for (int i = 0; i < 2; i++) {                 // A tile: 64x32
            int idx = tid + i * 256;
            int r = idx >> 3, q = idx & 7;
            int gr = row0 + r;
            float4 v = make_float4(0.f, 0.f, 0.f, 0.f);
            if (gr < N_NODES)
                v = *(const float4*)(A + (size_t)gr * 128 + kt + q * 4);
            *(float4*)&As[r][q * 4] = v;
        }
#pragma unroll
        for (int i = 0; i < 4; i++) {                 // W tile: 32x128
            int idx = tid + i * 256;
            int kr = idx >> 5, q = idx & 31;
            *(float4*)&Bs[kr][q * 4] =
                *(const float4*)(W + (size_t)(kt + kr) * 128 + q * 4);
        }
        __syncthreads();
#pragma unroll
        for (int k = 0; k < 32; k++) {
            float4 bv = *(float4*)&Bs[k][tc * 4];
#pragma unroll
            for (int i = 0; i < 8; i++) {
                float a = As[tr * 8 + i][k];          // warp-uniform -> broadcast
                acc[i].x += a * bv.x;
                acc[i].y += a * bv.y;
                acc[i].z += a * bv.z;
                acc[i].w += a * bv.w;
            }
        }
        __syncthreads();
    }
#pragma unroll
    for (int i = 0; i < 8; i++) {
        int gr = row0 + tr * 8 + i;
        if (gr < N_NODES) {
            float d = g_dinv[gr];
            float4 v = acc[i];
            v.x *= d; v.y *= d; v.z *= d; v.w *= d;
            *(float4*)(out + (size_t)gr * 128 + tc * 4) = v;
        }
    }
}

// ---------------- gather (pull): out[i] = relu(dinv[i]*(t[i]+sum t[j]) + b) --
// one warp per node, lane handles 4 contiguous cols (float4)
__global__ void __launch_bounds__(256) k_gather(
        const float* __restrict__ ts, const float* __restrict__ bias,
        float* __restrict__ out) {
    int w    = (blockIdx.x * blockDim.x + threadIdx.x) >> 5;
    int lane = threadIdx.x & 31;
    if (w >= N_NODES) return;

    const float* tsl = ts + 4 * lane;
    float4 acc = *(const float4*)(tsl + (size_t)w * 128);   // self-loop term

    int e0 = g_rowptr[w];
    int e1 = g_rowptr[w + 1];
    for (int eb = e0; eb < e1; eb += 32) {
        int cnt = e1 - eb; if (cnt > 32) cnt = 32;
        int s = (lane < cnt) ? g_srcs[eb + lane] : 0;
        for (int j = 0; j < cnt; j++) {
            int sj = __shfl_sync(0xffffffffu, s, j);
            float4 v = *(const float4*)(tsl + (size_t)sj * 128);
            acc.x += v.x; acc.y += v.y; acc.z += v.z; acc.w += v.w;
        }
    }
    float  d  = g_dinv[w];
    float4 bb = *(const float4*)(bias + 4 * lane);
    float4 o;
    o.x = fmaxf(acc.x * d + bb.x, 0.f);
    o.y = fmaxf(acc.y * d + bb.y, 0.f);
    o.z = fmaxf(acc.z * d + bb.z, 0.f);
    o.w = fmaxf(acc.w * d + bb.w, 0.f);
    *(float4*)(out + (size_t)w * 128 + 4 * lane) = o;
}

// ---------------- pooling: batch is sorted -> smem window accumulation -------
#define POOL_NODES 256
#define WIN 16
__global__ void __launch_bounds__(128) k_pool(
        const float* __restrict__ h, const int* __restrict__ batch) {
    int n0 = blockIdx.x * POOL_NODES;
    int n1 = n0 + POOL_NODES; if (n1 > N_NODES) n1 = N_NODES;
    if (n0 >= N_NODES) return;
    int c = threadIdx.x;                       // 128 threads, one col each

    __shared__ float sacc[WIN][128];
    __shared__ int   scnt[WIN];

    int b0 = batch[n0];
    int b1 = batch[n1 - 1];

    for (int wb = b0; wb <= b1; wb += WIN) {
        int we = wb + WIN - 1; if (we > b1) we = b1;
#pragma unroll
        for (int wi = 0; wi < WIN; wi++) sacc[wi][c] = 0.f;
        if (c < WIN) scnt[c] = 0;
        __syncthreads();
        for (int n = n0; n < n1; n++) {
            int g = batch[n];
            if (g >= wb && g <= we) {
                sacc[g - wb][c] += h[(size_t)n * 128 + c];
                if (c == 0) scnt[g - wb]++;
            }
        }
        __syncthreads();
        for (int wi = 0; wi <= we - wb; wi++)
            atomicAdd(&g_pool[(wb + wi) * 128 + c], sacc[wi][c]);
        if (c == 0)
            for (int wi = 0; wi <= we - wb; wi++)
                atomicAdd(&g_poolcnt[wb + wi], (float)scnt[wi]);
        __syncthreads();
    }
}

// ---------------- MLP head: out = relu(p@Wm1+bm1) @ Wm2 + bm2 ----------------
__global__ void __launch_bounds__(128) k_mlp(
        const float* __restrict__ Wm1, const float* __restrict__ bm1,
        const float* __restrict__ Wm2, const float* __restrict__ bm2,
        float* __restrict__ out) {
    int g = blockIdx.x;
    int t = threadIdx.x;
    __shared__ float p[128];
    __shared__ float z[64];
    float cnt = fmaxf(g_poolcnt[g], 1.f);
    p[t] = g_pool[g * 128 + t] / cnt;
    __syncthreads();
    if (t < 64) {
        float a = bm1[t];
#pragma unroll 8
        for (int c = 0; c < 128; c++) a += p[c] * Wm1[c * 64 + t];
        z[t] = fmaxf(a, 0.f);
    }
    __syncthreads();
    if (t < 32) {
        float a = bm2[t];
#pragma unroll 8
        for (int j = 0; j < 64; j++) a += z[j] * Wm2[j * 32 + t];
        out[g * 32 + t] = a;
    }
}

// ---------------- launch -----------------------------------------------------
extern "C" void kernel_launch(void* const* d_in, const int* in_sizes, int n_in,
                              void* d_out, int out_size) {
    // Resolve inputs by element count (robust to serialization order).
    // Sizes: x=12.8M, edge_index=3.2M, batch=100k, W*=16384 (x3, in order),
    // b*=128 (x3, in order), Wm1=8192, bm1=64, Wm2=2048, bm2=32.
    const float *x = 0, *W[3] = {0,0,0}, *b[3] = {0,0,0};
    const float *Wm1 = 0, *bm1 = 0, *Wm2 = 0, *bm2 = 0;
    const int *ei = 0, *batch = 0;
    int wi = 0, bi = 0;
    for (int i = 0; i < n_in; i++) {
        long long s = in_sizes[i];
        if      (s == (long long)N_NODES * HID) x     = (const float*)d_in[i];
        else if (s == 2LL * N_EDGES)            ei    = (const int*)d_in[i];
        else if (s == N_NODES)                  batch = (const int*)d_in[i];
        else if (s == HID * HID) { if (wi < 3) W[wi++] = (const float*)d_in[i]; }
        else if (s == HID)       { if (bi < 3) b[bi++] = (const float*)d_in[i]; }
        else if (s == HID * (HID / 2))          Wm1   = (const float*)d_in[i];
        else if (s == HID / 2)                  bm1   = (const float*)d_in[i];
        else if (s == (HID / 2) * 32)           Wm2   = (const float*)d_in[i];
        else if (s == 32)                       bm2   = (const float*)d_in[i];
    }
    float* out = (float*)d_out;

    float *buf0, *buf1, *buf2;
    cudaGetSymbolAddress((void**)&buf0, g_buf0);
    cudaGetSymbolAddress((void**)&buf1, g_buf1);
    cudaGetSymbolAddress((void**)&buf2, g_buf2);

    const int EB = (N_EDGES + 255) / 256;
    const int NB = (N_NODES + 255) / 256;
    const int GB = (N_NODES + 63) / 64;
    const int WB = (N_NODES * 32 + 255) / 256;
    const int PB = (N_NODES + POOL_NODES - 1) / POOL_NODES;

    k_init<<<NB, 256>>>();
    k_hist<<<EB, 256>>>(ei);
    k_scan<<<1, 1024>>>();
    k_fill<<<EB, 256>>>(ei);

    // layer 1: x -> buf1
    k_gemm_scale<<<GB, 256>>>(x, W[0], buf0);
    k_gather<<<WB, 256>>>(buf0, b[0], buf1);
    // layer 2: buf1 -> buf2
    k_gemm_scale<<<GB, 256>>>(buf1, W[1], buf0);
    k_gather<<<WB, 256>>>(buf0, b[1], buf2);
    // layer 3: buf2 -> buf1
    k_gemm_scale<<<GB, 256>>>(buf2, W[2], buf0);
    k_gather<<<WB, 256>>>(buf0, b[2], buf1);

    k_pool<<<PB, 128>>>(buf1, batch);
    k_mlp<<<NUM_GRAPHS, 128>>>(Wm1, bm1, Wm2, bm2, out);
}

// round 4
// speedup vs baseline: 1.0817x; 1.0787x over previous
#include <cuda_runtime.h>
#include <cuda_fp16.h>
#include <math.h>

#define N_NODES   100000
#define N_EDGES   1600000
#define NUM_GRAPHS 512
#define HID       128

// ---------------- static device scratch (no allocations allowed) -------------
__device__ __align__(16) __half g_tbuf[(size_t)N_NODES * HID];   // t^ = (AW)*dinv, fp16
__device__ __align__(16) float  g_buf1[(size_t)N_NODES * HID];   // activations ping
__device__ __align__(16) float  g_buf2[(size_t)N_NODES * HID];   // activations pong
__device__ float g_dinv[N_NODES];
__device__ int   g_cnt[N_NODES];
__device__ int   g_fill[N_NODES];
__device__ int   g_rowptr[N_NODES + 1];
__device__ int   g_srcs[N_EDGES];
__device__ float g_pool[NUM_GRAPHS * HID];
__device__ float g_poolcnt[NUM_GRAPHS];

// ---------------- init -------------------------------------------------------
__global__ void k_init() {
    int i = blockIdx.x * blockDim.x + threadIdx.x;
    if (i < N_NODES) { g_cnt[i] = 0; g_fill[i] = 0; }
    if (i < NUM_GRAPHS * HID) g_pool[i] = 0.f;
    if (i < NUM_GRAPHS) g_poolcnt[i] = 0.f;
}

// ---------------- degree histogram over edge targets -------------------------
__global__ void k_hist(const int* __restrict__ ei) {
    int e = blockIdx.x * blockDim.x + threadIdx.x;
    if (e < N_EDGES) atomicAdd(&g_cnt[ei[N_EDGES + e]], 1);
}

// ---------------- single-block exclusive scan + dinv -------------------------
__global__ void k_scan() {
    const int T = 1024;
    const int CH = (N_NODES + T - 1) / T;
    int t = threadIdx.x;
    int s = t * CH;
    int e = s + CH; if (e > N_NODES) e = N_NODES;

    int sum = 0;
    for (int i = s; i < e; i++) sum += g_cnt[i];

    __shared__ int ss[T];
    ss[t] = sum;
    __syncthreads();
    for (int off = 1; off < T; off <<= 1) {
        int v = (t >= off) ? ss[t - off] : 0;
        __syncthreads();
        ss[t] += v;
        __syncthreads();
    }
    int run = (t > 0) ? ss[t - 1] : 0;
    for (int i = s; i < e; i++) {
        int c = g_cnt[i];
        g_rowptr[i] = run;
        run += c;
        g_dinv[i] = rsqrtf((float)(c + 1));
    }
    if (t == T - 1) g_rowptr[N_NODES] = ss[T - 1];
}

// ---------------- CSR fill ---------------------------------------------------
__global__ void k_fill(const int* __restrict__ ei) {
    int e = blockIdx.x * blockDim.x + threadIdx.x;
    if (e < N_EDGES) {
        int row = ei[e];
        int col = ei[N_EDGES + e];
        int pos = g_rowptr[col] + atomicAdd(&g_fill[col], 1);
        g_srcs[pos] = row;
    }
}

// ---------------- GEMM: thalf = (A @ W) * dinv[row], stored fp16 -------------
__global__ void __launch_bounds__(256) k_gemm_scale(
        const float* __restrict__ A, const float* __restrict__ W,
        __half* __restrict__ out) {
    __shared__ float As[64][32];
    __shared__ float Bs[32][128];
    int tid  = threadIdx.x;
    int row0 = blockIdx.x * 64;
    int tr = tid >> 5;
    int tc = tid & 31;

    float4 acc[8];
#pragma unroll
    for (int i = 0; i < 8; i++) acc[i] = make_float4(0.f, 0.f, 0.f, 0.f);

    for (int kt = 0; kt < 128; kt += 32) {
#pragma unroll
        for (int i = 0; i < 2; i++) {
            int idx = tid + i * 256;
            int r = idx >> 3, q = idx & 7;
            int gr = row0 + r;
            float4 v = make_float4(0.f, 0.f, 0.f, 0.f);
            if (gr < N_NODES)
                v = *(const float4*)(A + (size_t)gr * 128 + kt + q * 4);
            *(float4*)&As[r][q * 4] = v;
        }
#pragma unroll
        for (int i = 0; i < 4; i++) {
            int idx = tid + i * 256;
            int kr = idx >> 5, q = idx & 31;
            *(float4*)&Bs[kr][q * 4] =
                *(const float4*)(W + (size_t)(kt + kr) * 128 + q * 4);
        }
        __syncthreads();
#pragma unroll
        for (int k = 0; k < 32; k++) {
            float4 bv = *(float4*)&Bs[k][tc * 4];
#pragma unroll
            for (int i = 0; i < 8; i++) {
                float a = As[tr * 8 + i][k];
                acc[i].x += a * bv.x;
                acc[i].y += a * bv.y;
                acc[i].z += a * bv.z;
                acc[i].w += a * bv.w;
            }
        }
        __syncthreads();
    }
#pragma unroll
    for (int i = 0; i < 8; i++) {
        int gr = row0 + tr * 8 + i;
        if (gr < N_NODES) {
            float d = g_dinv[gr];
            float4 v = acc[i];
            __half2 p0 = __floats2half2_rn(v.x * d, v.y * d);
            __half2 p1 = __floats2half2_rn(v.z * d, v.w * d);
            uint2 u;
            u.x = *reinterpret_cast<unsigned int*>(&p0);
            u.y = *reinterpret_cast<unsigned int*>(&p1);
            *(uint2*)(out + (size_t)gr * 128 + tc * 4) = u;
        }
    }
}

// ---------------- fp16 row -> float4 -----------------------------------------
__device__ __forceinline__ float4 h4_to_f4(uint2 u) {
    __half2 h0 = *reinterpret_cast<__half2*>(&u.x);
    __half2 h1 = *reinterpret_cast<__half2*>(&u.y);
    float2 f0 = __half22float2(h0);
    float2 f1 = __half22float2(h1);
    return make_float4(f0.x, f0.y, f1.x, f1.y);
}

// ---------------- gather (pull): out[i] = relu(dinv[i]*(t[i]+sum t[j]) + b) --
// one warp per node; lane handles 4 cols as fp16 (8B loads); 4x unrolled
__global__ void __launch_bounds__(256) k_gather(
        const __half* __restrict__ ts, const float* __restrict__ bias,
        float* __restrict__ out) {
    int w    = (blockIdx.x * blockDim.x + threadIdx.x) >> 5;
    int lane = threadIdx.x & 31;
    if (w >= N_NODES) return;

    const __half* tsl = ts + 4 * lane;
    float4 acc = h4_to_f4(*(const uint2*)(tsl + (size_t)w * 128));  // self term

    int e0 = g_rowptr[w];
    int e1 = g_rowptr[w + 1];
    for (int eb = e0; eb < e1; eb += 32) {
        int cnt = e1 - eb; if (cnt > 32) cnt = 32;
        int s = (lane < cnt) ? g_srcs[eb + lane] : 0;
        int j = 0;
        for (; j + 4 <= cnt; j += 4) {
            int s0 = __shfl_sync(0xffffffffu, s, j);
            int s1 = __shfl_sync(0xffffffffu, s, j + 1);
            int s2 = __shfl_sync(0xffffffffu, s, j + 2);
            int s3 = __shfl_sync(0xffffffffu, s, j + 3);
            uint2 u0 = *(const uint2*)(tsl + (size_t)s0 * 128);
            uint2 u1 = *(const uint2*)(tsl + (size_t)s1 * 128);
            uint2 u2 = *(const uint2*)(tsl + (size_t)s2 * 128);
            uint2 u3 = *(const uint2*)(tsl + (size_t)s3 * 128);
            float4 v0 = h4_to_f4(u0);
            float4 v1 = h4_to_f4(u1);
            float4 v2 = h4_to_f4(u2);
            float4 v3 = h4_to_f4(u3);
            acc.x += (v0.x + v1.x) + (v2.x + v3.x);
            acc.y += (v0.y + v1.y) + (v2.y + v3.y);
            acc.z += (v0.z + v1.z) + (v2.z + v3.z);
            acc.w += (v0.w + v1.w) + (v2.w + v3.w);
        }
        for (; j < cnt; j++) {
            int sj = __shfl_sync(0xffffffffu, s, j);
            float4 v = h4_to_f4(*(const uint2*)(tsl + (size_t)sj * 128));
            acc.x += v.x; acc.y += v.y; acc.z += v.z; acc.w += v.w;
        }
    }
    float  d  = g_dinv[w];
    float4 bb = *(const float4*)(bias + 4 * lane);
    float4 o;
    o.x = fmaxf(acc.x * d + bb.x, 0.f);
    o.y = fmaxf(acc.y * d + bb.y, 0.f);
    o.z = fmaxf(acc.z * d + bb.z, 0.f);
    o.w = fmaxf(acc.w * d + bb.w, 0.f);
    *(float4*)(out + (size_t)w * 128 + 4 * lane) = o;
}

// ---------------- pooling: batch sorted -> smem window accumulation ----------
#define POOL_NODES 256
#define WIN 16
__global__ void __launch_bounds__(128) k_pool(
        const float* __restrict__ h, const int* __restrict__ batch) {
    int n0 = blockIdx.x * POOL_NODES;
    int n1 = n0 + POOL_NODES; if (n1 > N_NODES) n1 = N_NODES;
    if (n0 >= N_NODES) return;
    int c = threadIdx.x;

    __shared__ float sacc[WIN][128];
    __shared__ int   scnt[WIN];

    int b0 = batch[n0];
    int b1 = batch[n1 - 1];

    for (int wb = b0; wb <= b1; wb += WIN) {
        int we = wb + WIN - 1; if (we > b1) we = b1;
#pragma unroll
        for (int wi = 0; wi < WIN; wi++) sacc[wi][c] = 0.f;
        if (c < WIN) scnt[c] = 0;
        __syncthreads();
        for (int n = n0; n < n1; n++) {
            int g = batch[n];
            if (g >= wb && g <= we) {
                sacc[g - wb][c] += h[(size_t)n * 128 + c];
                if (c == 0) scnt[g - wb]++;
            }
        }
        __syncthreads();
        for (int wi = 0; wi <= we - wb; wi++)
            atomicAdd(&g_pool[(wb + wi) * 128 + c], sacc[wi][c]);
        if (c == 0)
            for (int wi = 0; wi <= we - wb; wi++)
                atomicAdd(&g_poolcnt[wb + wi], (float)scnt[wi]);
        __syncthreads();
    }
}

// ---------------- MLP head ---------------------------------------------------
__global__ void __launch_bounds__(128) k_mlp(
        const float* __restrict__ Wm1, const float* __restrict__ bm1,
        const float* __restrict__ Wm2, const float* __restrict__ bm2,
        float* __restrict__ out) {
    int g = blockIdx.x;
    int t = threadIdx.x;
    __shared__ float p[128];
    __shared__ float z[64];
    float cnt = fmaxf(g_poolcnt[g], 1.f);
    p[t] = g_pool[g * 128 + t] / cnt;
    __syncthreads();
    if (t < 64) {
        float a = bm1[t];
#pragma unroll 8
        for (int c = 0; c < 128; c++) a += p[c] * Wm1[c * 64 + t];
        z[t] = fmaxf(a, 0.f);
    }
    __syncthreads();
    if (t < 32) {
        float a = bm2[t];
#pragma unroll 8
        for (int j = 0; j < 64; j++) a += z[j] * Wm2[j * 32 + t];
        out[g * 32 + t] = a;
    }
}

// ---------------- launch -----------------------------------------------------
extern "C" void kernel_launch(void* const* d_in, const int* in_sizes, int n_in,
                              void* d_out, int out_size) {
    const float *x = 0, *W[3] = {0,0,0}, *b[3] = {0,0,0};
    const float *Wm1 = 0, *bm1 = 0, *Wm2 = 0, *bm2 = 0;
    const int *ei = 0, *batch = 0;
    int wi = 0, bi = 0;
    for (int i = 0; i < n_in; i++) {
        long long s = in_sizes[i];
        if      (s == (long long)N_NODES * HID) x     = (const float*)d_in[i];
        else if (s == 2LL * N_EDGES)            ei    = (const int*)d_in[i];
        else if (s == N_NODES)                  batch = (const int*)d_in[i];
        else if (s == HID * HID) { if (wi < 3) W[wi++] = (const float*)d_in[i]; }
        else if (s == HID)       { if (bi < 3) b[bi++] = (const float*)d_in[i]; }
        else if (s == HID * (HID / 2))          Wm1   = (const float*)d_in[i];
        else if (s == HID / 2)                  bm1   = (const float*)d_in[i];
        else if (s == (HID / 2) * 32)           Wm2   = (const float*)d_in[i];
        else if (s == 32)                       bm2   = (const float*)d_in[i];
    }
    float* out = (float*)d_out;

    __half *tbuf;
    float *buf1, *buf2;
    cudaGetSymbolAddress((void**)&tbuf, g_tbuf);
    cudaGetSymbolAddress((void**)&buf1, g_buf1);
    cudaGetSymbolAddress((void**)&buf2, g_buf2);

    const int EB = (N_EDGES + 255) / 256;
    const int NB = (N_NODES + 255) / 256;
    const int GB = (N_NODES + 63) / 64;
    const int WB = (N_NODES * 32 + 255) / 256;
    const int PB = (N_NODES + POOL_NODES - 1) / POOL_NODES;

    k_init<<<NB, 256>>>();
    k_hist<<<EB, 256>>>(ei);
    k_scan<<<1, 1024>>>();
    k_fill<<<EB, 256>>>(ei);

    // layer 1: x -> buf1
    k_gemm_scale<<<GB, 256>>>(x, W[0], tbuf);
    k_gather<<<WB, 256>>>(tbuf, b[0], buf1);
    // layer 2: buf1 -> buf2
    k_gemm_scale<<<GB, 256>>>(buf1, W[1], tbuf);
    k_gather<<<WB, 256>>>(tbuf, b[1], buf2);
    // layer 3: buf2 -> buf1
    k_gemm_scale<<<GB, 256>>>(buf2, W[2], tbuf);
    k_gather<<<WB, 256>>>(tbuf, b[2], buf1);

    k_pool<<<PB, 128>>>(buf1, batch);
    k_mlp<<<NUM_GRAPHS, 128>>>(Wm1, bm1, Wm2, bm2, out);
}

// round 6
// speedup vs baseline: 1.6350x; 1.5116x over previous
#include <cuda_runtime.h>
#include <cuda_fp16.h>
#include <math.h>

#define N_NODES   100000
#define N_EDGES   1600000
#define NUM_GRAPHS 512
#define HID       128

#define SCAN_BLKS 125
#define SCAN_CH   800          // SCAN_BLKS * SCAN_CH == N_NODES

// ---------------- static device scratch --------------------------------------
__device__ __align__(16) __half g_tbuf[(size_t)N_NODES * HID];  // t^ = (AW)*dinv
__device__ __align__(16) __half g_hbuf[(size_t)N_NODES * HID];  // fp16 activations
__device__ __align__(16) float  g_fbuf[(size_t)N_NODES * HID];  // layer-3 out (fp32)
__device__ float g_dinv[N_NODES];
__device__ int   g_cnt[N_NODES];
__device__ int   g_fill[N_NODES];
__device__ int   g_rowptr[N_NODES + 1];
__device__ int   g_srcs[N_EDGES];
__device__ int   g_part[SCAN_BLKS];
__device__ float g_pool[NUM_GRAPHS * HID];
__device__ float g_poolcnt[NUM_GRAPHS];

// ---------------- init -------------------------------------------------------
__global__ void k_init() {
    int i = blockIdx.x * blockDim.x + threadIdx.x;
    if (i < N_NODES) { g_cnt[i] = 0; g_fill[i] = 0; }
    if (i < NUM_GRAPHS * HID) g_pool[i] = 0.f;
    if (i < NUM_GRAPHS) g_poolcnt[i] = 0.f;
}

// ---------------- degree histogram -------------------------------------------
__global__ void k_hist(const int* __restrict__ ei) {
    int e = blockIdx.x * blockDim.x + threadIdx.x;
    if (e < N_EDGES) atomicAdd(&g_cnt[ei[N_EDGES + e]], 1);
}

// ---------------- scan phase 1: per-block partial sums ------------------------
__global__ void __launch_bounds__(256) k_scan1() {
    int b = blockIdx.x, t = threadIdx.x;
    int base = b * SCAN_CH;
    int sum = 0;
    for (int i = t; i < SCAN_CH; i += 256) sum += g_cnt[base + i];
    __shared__ int ss[256];
    ss[t] = sum;
    __syncthreads();
    for (int off = 128; off > 0; off >>= 1) {
        if (t < off) ss[t] += ss[t + off];
        __syncthreads();
    }
    if (t == 0) g_part[b] = ss[0];
}

// ---------------- scan phase 2: per-block exclusive scan + dinv ---------------
__global__ void __launch_bounds__(256) k_scan2() {
    int b = blockIdx.x, t = threadIdx.x;
    __shared__ int sbase;
    if (t == 0) {
        int r = 0;
        for (int i = 0; i < b; i++) r += g_part[i];
        sbase = r;
    }
    int s = b * SCAN_CH + t * 4;
    int c[4] = {0, 0, 0, 0};
    int sum = 0;
    bool act = (t * 4 < SCAN_CH);
    if (act) {
#pragma unroll
        for (int j = 0; j < 4; j++) { c[j] = g_cnt[s + j]; sum += c[j]; }
    }
    __shared__ int ss[256];
    ss[t] = sum;
    __syncthreads();
    for (int off = 1; off < 256; off <<= 1) {
        int v = (t >= off) ? ss[t - off] : 0;
        __syncthreads();
        ss[t] += v;
        __syncthreads();
    }
    if (act) {
        int run = sbase + (t > 0 ? ss[t - 1] : 0);
#pragma unroll
        for (int j = 0; j < 4; j++) {
            g_rowptr[s + j] = run;
            run += c[j];
            g_dinv[s + j] = rsqrtf((float)(c[j] + 1));
        }
    }
    if (b == SCAN_BLKS - 1 && t == 255) g_rowptr[N_NODES] = sbase + ss[255];
}

// ---------------- CSR fill ---------------------------------------------------
__global__ void k_fill(const int* __restrict__ ei) {
    int e = blockIdx.x * blockDim.x + threadIdx.x;
    if (e < N_EDGES) {
        int row = ei[e];
        int col = ei[N_EDGES + e];
        int pos = g_rowptr[col] + atomicAdd(&g_fill[col], 1);
        g_srcs[pos] = row;
    }
}

// ---------------- tensor-core GEMM: out = half((A @ W) * dinv[row]) ----------
// block: 128 rows x 128 cols, 256 thr (8 warps of 32x64). A,Wt in smem fp16.
#define ROWP 136                              // padded row stride (halves)
#define GEMM_SMEM (2 * 128 * ROWP * 2)        // bytes

__device__ __forceinline__ void mma16816(float* c, const unsigned* a,
                                         unsigned b0, unsigned b1) {
    asm volatile(
        "mma.sync.aligned.m16n8k16.row.col.f32.f16.f16.f32 "
        "{%0,%1,%2,%3}, {%4,%5,%6,%7}, {%8,%9}, {%0,%1,%2,%3};\n"
        : "+f"(c[0]), "+f"(c[1]), "+f"(c[2]), "+f"(c[3])
        : "r"(a[0]), "r"(a[1]), "r"(a[2]), "r"(a[3]), "r"(b0), "r"(b1));
}

template <typename InT>
__global__ void __launch_bounds__(256) k_gemm_tc(
        const InT* __restrict__ A, const float* __restrict__ W,
        __half* __restrict__ out) {
    extern __shared__ __half sm[];
    __half* As = sm;                 // [128][ROWP]
    __half* Ws = sm + 128 * ROWP;    // Wt: [n][k] [128][ROWP]
    int tid = threadIdx.x;
    int row0 = blockIdx.x * 128;

    // ---- load A tile (convert to fp16 if needed), zero OOB rows ----
#pragma unroll
    for (int it = 0; it < 8; it++) {
        int idx = tid + it * 256;            // 0..2047
        int r = idx >> 4, c8 = (idx & 15) << 3;
        int gr = row0 + r;
        uint4 u = make_uint4(0, 0, 0, 0);
        if (gr < N_NODES) {
            if constexpr (sizeof(InT) == 2) {
                u = *(const uint4*)((const __half*)A + (size_t)gr * 128 + c8);
            } else {
                const float* ap = (const float*)A + (size_t)gr * 128 + c8;
                float4 f0 = *(const float4*)ap;
                float4 f1 = *(const float4*)(ap + 4);
                __half2 h0 = __floats2half2_rn(f0.x, f0.y);
                __half2 h1 = __floats2half2_rn(f0.z, f0.w);
                __half2 h2 = __floats2half2_rn(f1.x, f1.y);
                __half2 h3 = __floats2half2_rn(f1.z, f1.w);
                u.x = *(unsigned*)&h0; u.y = *(unsigned*)&h1;
                u.z = *(unsigned*)&h2; u.w = *(unsigned*)&h3;
            }
        }
        *(uint4*)(As + r * ROWP + c8) = u;
    }
    // ---- load W transposed (Wt[n][k] = W[k][n]) as fp16 ----
#pragma unroll
    for (int it = 0; it < 8; it++) {
        int idx = tid + it * 256;            // 0..2047
        int n = idx >> 4, kg = (idx & 15) << 3;
        __half h[8];
#pragma unroll
        for (int i = 0; i < 8; i++)
            h[i] = __float2half(W[(size_t)(kg + i) * 128 + n]);
        *(uint4*)(Ws + n * ROWP + kg) = *(uint4*)h;
    }
    __syncthreads();

    int wid = tid >> 5, lane = tid & 31;
    int wm = wid & 3, wn = wid >> 2;          // warp tile: rows wm*32, cols wn*64
    int g = lane >> 2, tig = lane & 3;

    float acc[2][8][4] = {};
#pragma unroll
    for (int ks = 0; ks < 8; ks++) {
        int kc = ks * 16 + tig * 2;
        unsigned a[2][4];
#pragma unroll
        for (int mi = 0; mi < 2; mi++) {
            int r = wm * 32 + mi * 16 + g;
            a[mi][0] = *(unsigned*)(As + r * ROWP + kc);
            a[mi][1] = *(unsigned*)(As + (r + 8) * ROWP + kc);
            a[mi][2] = *(unsigned*)(As + r * ROWP + kc + 8);
            a[mi][3] = *(unsigned*)(As + (r + 8) * ROWP + kc + 8);
        }
#pragma unroll
        for (int ni = 0; ni < 8; ni++) {
            int n = wn * 64 + ni * 8 + g;
            unsigned b0 = *(unsigned*)(Ws + n * ROWP + kc);
            unsigned b1 = *(unsigned*)(Ws + n * ROWP + kc + 8);
#pragma unroll
            for (int mi = 0; mi < 2; mi++)
                mma16816(acc[mi][ni], a[mi], b0, b1);
        }
    }
    // ---- epilogue: scale by dinv, convert fp16, store ----
#pragma unroll
    for (int mi = 0; mi < 2; mi++) {
        int r = row0 + wm * 32 + mi * 16 + g;
        int r2 = r + 8;
        float d0 = (r < N_NODES) ? g_dinv[r] : 0.f;
        float d1 = (r2 < N_NODES) ? g_dinv[r2] : 0.f;
#pragma unroll
        for (int ni = 0; ni < 8; ni++) {
            int c = wn * 64 + ni * 8 + tig * 2;
            if (r < N_NODES) {
                __half2 h = __floats2half2_rn(acc[mi][ni][0] * d0,
                                              acc[mi][ni][1] * d0);
                *(__half2*)(out + (size_t)r * 128 + c) = h;
            }
            if (r2 < N_NODES) {
                __half2 h = __floats2half2_rn(acc[mi][ni][2] * d1,
                                              acc[mi][ni][3] * d1);
                *(__half2*)(out + (size_t)r2 * 128 + c) = h;
            }
        }
    }
}

// ---------------- gather: half-warp (16 lanes) per node, uint4 loads ---------
__device__ __forceinline__ void acc8(float* acc, uint4 u) {
    __half2* h = (__half2*)&u;
    float2 f;
    f = __half22float2(h[0]); acc[0] += f.x; acc[1] += f.y;
    f = __half22float2(h[1]); acc[2] += f.x; acc[3] += f.y;
    f = __half22float2(h[2]); acc[4] += f.x; acc[5] += f.y;
    f = __half22float2(h[3]); acc[6] += f.x; acc[7] += f.y;
}

template <typename OutT>
__global__ void __launch_bounds__(256) k_gather(
        const __half* __restrict__ ts, const float* __restrict__ bias,
        OutT* __restrict__ out) {
    int node = blockIdx.x * 16 + (threadIdx.x >> 4);
    int lane = threadIdx.x & 31;
    int sub  = threadIdx.x & 15;
    if (node >= N_NODES) return;
    unsigned gmask = 0xFFFFu << (lane & 0x10);
    int gbase = lane & 0x10;

    const __half* tsl = ts + 8 * sub;
    float acc[8] = {0, 0, 0, 0, 0, 0, 0, 0};
    acc8(acc, *(const uint4*)(tsl + (size_t)node * 128));   // self-loop term

    int e0 = g_rowptr[node];
    int e1 = g_rowptr[node + 1];
    for (int eb = e0; eb < e1; eb += 16) {
        int cnt = e1 - eb; if (cnt > 16) cnt = 16;
        int s = (sub < cnt) ? g_srcs[eb + sub] : 0;
        int j = 0;
        for (; j + 4 <= cnt; j += 4) {
            int s0 = __shfl_sync(gmask, s, gbase + j);
            int s1 = __shfl_sync(gmask, s, gbase + j + 1);
            int s2 = __shfl_sync(gmask, s, gbase + j + 2);
            int s3 = __shfl_sync(gmask, s, gbase + j + 3);
            uint4 u0 = *(const uint4*)(tsl + (size_t)s0 * 128);
            uint4 u1 = *(const uint4*)(tsl + (size_t)s1 * 128);
            uint4 u2 = *(const uint4*)(tsl + (size_t)s2 * 128);
            uint4 u3 = *(const uint4*)(tsl + (size_t)s3 * 128);
            acc8(acc, u0); acc8(acc, u1); acc8(acc, u2); acc8(acc, u3);
        }
        for (; j < cnt; j++) {
            int sj = __shfl_sync(gmask, s, gbase + j);
            acc8(acc, *(const uint4*)(tsl + (size_t)sj * 128));
        }
    }
    float d = g_dinv[node];
    float4 b0 = *(const float4*)(bias + 8 * sub);
    float4 b1 = *(const float4*)(bias + 8 * sub + 4);
    float o[8];
    o[0] = fmaxf(acc[0] * d + b0.x, 0.f);
    o[1] = fmaxf(acc[1] * d + b0.y, 0.f);
    o[2] = fmaxf(acc[2] * d + b0.z, 0.f);
    o[3] = fmaxf(acc[3] * d + b0.w, 0.f);
    o[4] = fmaxf(acc[4] * d + b1.x, 0.f);
    o[5] = fmaxf(acc[5] * d + b1.y, 0.f);
    o[6] = fmaxf(acc[6] * d + b1.z, 0.f);
    o[7] = fmaxf(acc[7] * d + b1.w, 0.f);
    if constexpr (sizeof(OutT) == 2) {
        __half2 h[4];
        h[0] = __floats2half2_rn(o[0], o[1]);
        h[1] = __floats2half2_rn(o[2], o[3]);
        h[2] = __floats2half2_rn(o[4], o[5]);
        h[3] = __floats2half2_rn(o[6], o[7]);
        *(uint4*)((__half*)out + (size_t)node * 128 + 8 * sub) = *(uint4*)h;
    } else {
        float* op = (float*)out + (size_t)node * 128 + 8 * sub;
        *(float4*)op       = make_float4(o[0], o[1], o[2], o[3]);
        *(float4*)(op + 4) = make_float4(o[4], o[5], o[6], o[7]);
    }
}

// ---------------- pooling: batch sorted -> smem window accumulation ----------
#define POOL_NODES 256
#define WIN 16
__global__ void __launch_bounds__(128) k_pool(
        const float* __restrict__ h, const int* __restrict__ batch) {
    int n0 = blockIdx.x * POOL_NODES;
    int n1 = n0 + POOL_NODES; if (n1 > N_NODES) n1 = N_NODES;
    if (n0 >= N_NODES) return;
    int c = threadIdx.x;

    __shared__ float sacc[WIN][128];
    __shared__ int   scnt[WIN];

    int b0 = batch[n0];
    int b1 = batch[n1 - 1];

    for (int wb = b0; wb <= b1; wb += WIN) {
        int we = wb + WIN - 1; if (we > b1) we = b1;
#pragma unroll
        for (int wi = 0; wi < WIN; wi++) sacc[wi][c] = 0.f;
        if (c < WIN) scnt[c] = 0;
        __syncthreads();
        for (int n = n0; n < n1; n++) {
            int g = batch[n];
            if (g >= wb && g <= we) {
                sacc[g - wb][c] += h[(size_t)n * 128 + c];
                if (c == 0) scnt[g - wb]++;
            }
        }
        __syncthreads();
        for (int wi = 0; wi <= we - wb; wi++)
            atomicAdd(&g_pool[(wb + wi) * 128 + c], sacc[wi][c]);
        if (c == 0)
            for (int wi = 0; wi <= we - wb; wi++)
                atomicAdd(&g_poolcnt[wb + wi], (float)scnt[wi]);
        __syncthreads();
    }
}

// ---------------- MLP head ---------------------------------------------------
__global__ void __launch_bounds__(128) k_mlp(
        const float* __restrict__ Wm1, const float* __restrict__ bm1,
        const float* __restrict__ Wm2, const float* __restrict__ bm2,
        float* __restrict__ out) {
    int g = blockIdx.x;
    int t = threadIdx.x;
    __shared__ float p[128];
    __shared__ float z[64];
    float cnt = fmaxf(g_poolcnt[g], 1.f);
    p[t] = g_pool[g * 128 + t] / cnt;
    __syncthreads();
    if (t < 64) {
        float a = bm1[t];
#pragma unroll 8
        for (int c = 0; c < 128; c++) a += p[c] * Wm1[c * 64 + t];
        z[t] = fmaxf(a, 0.f);
    }
    __syncthreads();
    if (t < 32) {
        float a = bm2[t];
#pragma unroll 8
        for (int j = 0; j < 64; j++) a += z[j] * Wm2[j * 32 + t];
        out[g * 32 + t] = a;
    }
}

// ---------------- launch -----------------------------------------------------
extern "C" void kernel_launch(void* const* d_in, const int* in_sizes, int n_in,
                              void* d_out, int out_size) {
    const float *x = 0, *W[3] = {0,0,0}, *b[3] = {0,0,0};
    const float *Wm1 = 0, *bm1 = 0, *Wm2 = 0, *bm2 = 0;
    const int *ei = 0, *batch = 0;
    int wi = 0, bi = 0;
    for (int i = 0; i < n_in; i++) {
        long long s = in_sizes[i];
        if      (s == (long long)N_NODES * HID) x     = (const float*)d_in[i];
        else if (s == 2LL * N_EDGES)            ei    = (const int*)d_in[i];
        else if (s == N_NODES)                  batch = (const int*)d_in[i];
        else if (s == HID * HID) { if (wi < 3) W[wi++] = (const float*)d_in[i]; }
        else if (s == HID)       { if (bi < 3) b[bi++] = (const float*)d_in[i]; }
        else if (s == HID * (HID / 2))          Wm1   = (const float*)d_in[i];
        else if (s == HID / 2)                  bm1   = (const float*)d_in[i];
        else if (s == (HID / 2) * 32)           Wm2   = (const float*)d_in[i];
        else if (s == 32)                       bm2   = (const float*)d_in[i];
    }
    float* out = (float*)d_out;

    __half *tbuf, *hbuf;
    float *fbuf;
    cudaGetSymbolAddress((void**)&tbuf, g_tbuf);
    cudaGetSymbolAddress((void**)&hbuf, g_hbuf);
    cudaGetSymbolAddress((void**)&fbuf, g_fbuf);

    // host-side attribute set — legal during capture (not a stream op),
    // called unconditionally (no static guards allowed)
    cudaFuncSetAttribute(k_gemm_tc<float>,
        cudaFuncAttributeMaxDynamicSharedMemorySize, GEMM_SMEM);
    cudaFuncSetAttribute(k_gemm_tc<__half>,
        cudaFuncAttributeMaxDynamicSharedMemorySize, GEMM_SMEM);

    const int EB = (N_EDGES + 255) / 256;
    const int NB = (N_NODES + 255) / 256;
    const int GB = (N_NODES + 127) / 128;
    const int WB = (N_NODES + 15) / 16;
    const int PB = (N_NODES + POOL_NODES - 1) / POOL_NODES;

    k_init<<<NB, 256>>>();
    k_hist<<<EB, 256>>>(ei);
    k_scan1<<<SCAN_BLKS, 256>>>();
    k_scan2<<<SCAN_BLKS, 256>>>();
    k_fill<<<EB, 256>>>(ei);

    // layer 1: x (fp32) -> tbuf -> hbuf
    k_gemm_tc<float><<<GB, 256, GEMM_SMEM>>>(x, W[0], tbuf);
    k_gather<__half><<<WB, 256>>>(tbuf, b[0], hbuf);
    // layer 2: hbuf -> tbuf -> hbuf
    k_gemm_tc<__half><<<GB, 256, GEMM_SMEM>>>(hbuf, W[1], tbuf);
    k_gather<__half><<<WB, 256>>>(tbuf, b[1], hbuf);
    // layer 3: hbuf -> tbuf -> fbuf (fp32 for pooling)
    k_gemm_tc<__half><<<GB, 256, GEMM_SMEM>>>(hbuf, W[2], tbuf);
    k_gather<float><<<WB, 256>>>(tbuf, b[2], fbuf);

    k_pool<<<PB, 128>>>(fbuf, batch);
    k_mlp<<<NUM_GRAPHS, 128>>>(Wm1, bm1, Wm2, bm2, out);
}